// round 1
// baseline (speedup 1.0000x reference)
#include <cuda_runtime.h>
#include <math.h>

#define BB 2
#define SS 2048
#define DD 512
#define HH 8
#define DK 64
#define M_TOTAL (BB*SS)   // 4096

// Scratch (allocation-free): Q/K/V head-split [B,H,S,DK], attn output [B,S,D]
__device__ float g_Q[BB*HH*SS*DK];
__device__ float g_K[BB*HH*SS*DK];
__device__ float g_V[BB*HH*SS*DK];
__device__ float g_attn[BB*SS*DD];

// ---------------------------------------------------------------------------
// C[M,N] = (A[M,K] @ W[N,K]^T + bias[N]) * alpha
// MODE 0: C row-major [M,N].  MODE 1: head-split store to [B,H,S,DK].
// M=4096, N=512, K=512. Tile 64x64, BK=16, 256 threads, 4x4 per thread.
// ---------------------------------------------------------------------------
template<int MODE>
__global__ __launch_bounds__(256)
void gemm_bias_kernel(const float* __restrict__ A,
                      const float* __restrict__ W,
                      const float* __restrict__ bias,
                      float* __restrict__ C,
                      float alpha) {
    __shared__ float As[64][17];
    __shared__ float Bs[64][17];

    const int tid = threadIdx.x;
    const int tx = tid & 15;
    const int ty = tid >> 4;
    const int m0 = blockIdx.y * 64;
    const int n0 = blockIdx.x * 64;

    float acc[4][4] = {};

    for (int kt = 0; kt < 512; kt += 16) {
        // Load 64x16 tiles of A and W; one float4 per thread each.
        {
            const int idx = tid * 4;
            const int m = idx >> 4;
            const int k = idx & 15;
            float4 a = *(const float4*)(A + (size_t)(m0 + m) * 512 + kt + k);
            As[m][k]   = a.x; As[m][k+1] = a.y; As[m][k+2] = a.z; As[m][k+3] = a.w;
            float4 b = *(const float4*)(W + (size_t)(n0 + m) * 512 + kt + k);
            Bs[m][k]   = b.x; Bs[m][k+1] = b.y; Bs[m][k+2] = b.z; Bs[m][k+3] = b.w;
        }
        __syncthreads();

        #pragma unroll
        for (int k = 0; k < 16; k++) {
            float a[4], b[4];
            #pragma unroll
            for (int i = 0; i < 4; i++) a[i] = As[ty*4 + i][k];
            #pragma unroll
            for (int j = 0; j < 4; j++) b[j] = Bs[tx*4 + j][k];
            #pragma unroll
            for (int i = 0; i < 4; i++)
                #pragma unroll
                for (int j = 0; j < 4; j++)
                    acc[i][j] = fmaf(a[i], b[j], acc[i][j]);
        }
        __syncthreads();
    }

    #pragma unroll
    for (int i = 0; i < 4; i++) {
        const int m = m0 + ty*4 + i;
        #pragma unroll
        for (int j = 0; j < 4; j++) {
            const int n = n0 + tx*4 + j;
            const float v = (acc[i][j] + bias[n]) * alpha;
            if (MODE == 0) {
                C[(size_t)m * 512 + n] = v;
            } else {
                const int b_ = m >> 11;          // m / 2048
                const int s_ = m & 2047;
                const int h_ = n >> 6;           // n / 64
                const int dk = n & 63;
                C[(((size_t)(b_ * HH + h_)) * SS + s_) * DK + dk] = v;
            }
        }
    }
}

// ---------------------------------------------------------------------------
// Flash-style attention. One CTA per (bh, 64-row q tile). 256 threads (16x16),
// 4x4 micro-tiles, online softmax. Scale 1/sqrt(DK) is pre-folded into Q.
// Output written directly in [B,S,D] layout for the final projection.
// ---------------------------------------------------------------------------
__global__ __launch_bounds__(256)
void attn_kernel(const float* __restrict__ Q,
                 const float* __restrict__ K,
                 const float* __restrict__ V,
                 float* __restrict__ Out) {
    extern __shared__ float sm[];
    float (*Qs)[64] = (float(*)[64])sm;                        // 64x64
    float (*Ks)[65] = (float(*)[65])(sm + 64*64);              // 64x65
    float (*Vs)[65] = (float(*)[65])(sm + 64*64 + 64*65);      // 64x65
    float (*Ps)[65] = (float(*)[65])(sm + 64*64 + 2*64*65);    // 64x65

    const int tid = threadIdx.x;
    const int tx = tid & 15;
    const int ty = tid >> 4;
    const int qt = blockIdx.x;   // 0..31
    const int bh = blockIdx.y;   // 0..15

    const float* Qb = Q + (size_t)bh * SS * DK + (size_t)qt * 64 * DK;
    const float* Kb = K + (size_t)bh * SS * DK;
    const float* Vb = V + (size_t)bh * SS * DK;

    // Load Q tile (resident for the whole CTA)
    for (int i = tid; i < 64*16; i += 256) {
        const int r = i >> 4;
        const int c = (i & 15) * 4;
        float4 v = *(const float4*)(Qb + r*64 + c);
        Qs[r][c] = v.x; Qs[r][c+1] = v.y; Qs[r][c+2] = v.z; Qs[r][c+3] = v.w;
    }

    float m_r[4], l_r[4], O[4][4];
    #pragma unroll
    for (int i = 0; i < 4; i++) {
        m_r[i] = -1e30f;
        l_r[i] = 0.0f;
        #pragma unroll
        for (int j = 0; j < 4; j++) O[i][j] = 0.0f;
    }

    for (int kt = 0; kt < 32; kt++) {
        __syncthreads();   // previous iteration's Ps/Vs reads done
        for (int i = tid; i < 64*16; i += 256) {
            const int r = i >> 4;
            const int c = (i & 15) * 4;
            float4 kv = *(const float4*)(Kb + (size_t)(kt*64 + r)*64 + c);
            Ks[r][c] = kv.x; Ks[r][c+1] = kv.y; Ks[r][c+2] = kv.z; Ks[r][c+3] = kv.w;
            float4 vv = *(const float4*)(Vb + (size_t)(kt*64 + r)*64 + c);
            Vs[r][c] = vv.x; Vs[r][c+1] = vv.y; Vs[r][c+2] = vv.z; Vs[r][c+3] = vv.w;
        }
        __syncthreads();

        // S = Q K^T (Q already scaled by 1/8)
        float sc[4][4] = {};
        #pragma unroll 8
        for (int k = 0; k < 64; k++) {
            float a[4], b[4];
            #pragma unroll
            for (int i = 0; i < 4; i++) a[i] = Qs[ty*4 + i][k];
            #pragma unroll
            for (int j = 0; j < 4; j++) b[j] = Ks[tx*4 + j][k];
            #pragma unroll
            for (int i = 0; i < 4; i++)
                #pragma unroll
                for (int j = 0; j < 4; j++)
                    sc[i][j] = fmaf(a[i], b[j], sc[i][j]);
        }

        // Online softmax update (row groups = 16 lanes sharing ty)
        #pragma unroll
        for (int i = 0; i < 4; i++) {
            float mx = sc[i][0];
            #pragma unroll
            for (int j = 1; j < 4; j++) mx = fmaxf(mx, sc[i][j]);
            #pragma unroll
            for (int off = 8; off > 0; off >>= 1)
                mx = fmaxf(mx, __shfl_xor_sync(0xffffffffu, mx, off, 16));

            const float mn = fmaxf(m_r[i], mx);
            const float corr = __expf(m_r[i] - mn);
            m_r[i] = mn;

            float rs = 0.0f;
            #pragma unroll
            for (int j = 0; j < 4; j++) {
                sc[i][j] = __expf(sc[i][j] - mn);
                rs += sc[i][j];
            }
            #pragma unroll
            for (int off = 8; off > 0; off >>= 1)
                rs += __shfl_xor_sync(0xffffffffu, rs, off, 16);

            l_r[i] = l_r[i] * corr + rs;
            #pragma unroll
            for (int j = 0; j < 4; j++) {
                O[i][j] *= corr;
                Ps[ty*4 + i][tx*4 + j] = sc[i][j];
            }
        }
        __syncthreads();

        // O += P @ V
        #pragma unroll 8
        for (int k = 0; k < 64; k++) {
            float a[4], b[4];
            #pragma unroll
            for (int i = 0; i < 4; i++) a[i] = Ps[ty*4 + i][k];
            #pragma unroll
            for (int j = 0; j < 4; j++) b[j] = Vs[k][tx*4 + j];
            #pragma unroll
            for (int i = 0; i < 4; i++)
                #pragma unroll
                for (int j = 0; j < 4; j++)
                    O[i][j] = fmaf(a[i], b[j], O[i][j]);
        }
    }

    // Normalize and write in [B,S,D] layout (heads re-interleaved)
    const int b_ = bh >> 3;
    const int h_ = bh & 7;
    #pragma unroll
    for (int i = 0; i < 4; i++) {
        const int s_ = qt*64 + ty*4 + i;
        const float inv = 1.0f / l_r[i];
        #pragma unroll
        for (int j = 0; j < 4; j++) {
            Out[((size_t)(b_ * SS + s_)) * DD + h_*64 + tx*4 + j] = O[i][j] * inv;
        }
    }
}

// ---------------------------------------------------------------------------

extern "C" void kernel_launch(void* const* d_in, const int* in_sizes, int n_in,
                              void* d_out, int out_size) {
    const float* x  = (const float*)d_in[0];
    const float* Wq = (const float*)d_in[1];
    const float* bq = (const float*)d_in[2];
    const float* Wk = (const float*)d_in[3];
    const float* bk = (const float*)d_in[4];
    const float* Wv = (const float*)d_in[5];
    const float* bv = (const float*)d_in[6];
    const float* Wo = (const float*)d_in[7];
    const float* bo = (const float*)d_in[8];
    float* out = (float*)d_out;

    float *Q, *K, *V, *attn;
    cudaGetSymbolAddress((void**)&Q, g_Q);
    cudaGetSymbolAddress((void**)&K, g_K);
    cudaGetSymbolAddress((void**)&V, g_V);
    cudaGetSymbolAddress((void**)&attn, g_attn);

    const dim3 gg(512/64, M_TOTAL/64);   // (8, 64)

    // QKV projections; 1/sqrt(64) folded into Q epilogue
    gemm_bias_kernel<1><<<gg, 256>>>(x, Wq, bq, Q, 0.125f);
    gemm_bias_kernel<1><<<gg, 256>>>(x, Wk, bk, K, 1.0f);
    gemm_bias_kernel<1><<<gg, 256>>>(x, Wv, bv, V, 1.0f);

    // Attention
    const size_t smem = (64*64 + 3*64*65) * sizeof(float);   // 66304 B
    cudaFuncSetAttribute(attn_kernel, cudaFuncAttributeMaxDynamicSharedMemorySize, (int)smem);
    attn_kernel<<<dim3(32, 16), 256, smem>>>(Q, K, V, attn);

    // Output projection
    gemm_bias_kernel<0><<<gg, 256>>>(attn, Wo, bo, out, 1.0f);
}

// round 2
// speedup vs baseline: 3.0181x; 3.0181x over previous
#include <cuda_runtime.h>
#include <math.h>

#define BB 2
#define SS 2048
#define DD 512
#define HH 8
#define DK 64
#define M_TOTAL (BB*SS)   // 4096

// Scratch (allocation-free)
__device__ float g_Q[BB*HH*SS*DK];
__device__ float g_K[BB*HH*SS*DK];
__device__ float g_V[BB*HH*SS*DK];
__device__ float g_attn[BB*SS*DD];

// ---------------------------------------------------------------------------
// helpers
// ---------------------------------------------------------------------------
__device__ __forceinline__ unsigned f2t(float x) {
    unsigned r;
    asm("cvt.rna.tf32.f32 %0, %1;" : "=r"(r) : "f"(x));
    return r;
}

__device__ __forceinline__ void mma8(float* c,
                                     unsigned a0, unsigned a1, unsigned a2, unsigned a3,
                                     unsigned b0, unsigned b1) {
    asm volatile(
        "mma.sync.aligned.m16n8k8.row.col.f32.tf32.tf32.f32 "
        "{%0,%1,%2,%3}, {%4,%5,%6,%7}, {%8,%9}, {%0,%1,%2,%3};"
        : "+f"(c[0]), "+f"(c[1]), "+f"(c[2]), "+f"(c[3])
        : "r"(a0), "r"(a1), "r"(a2), "r"(a3), "r"(b0), "r"(b1));
}

// ---------------------------------------------------------------------------
// C[M,N] = (A[M,K] @ W[N,K]^T + bias[N]) * alpha  via 3xTF32 mma.
// M=4096, N=512, K=512. Block 128x64, BK=32, 8 warps (4x2), warp tile 32x32.
// MODE 0: row-major [M,N].  MODE 1: head-split [B,H,S,DK].
// ---------------------------------------------------------------------------
template<int MODE>
__global__ __launch_bounds__(256)
void proj_kernel(const float* __restrict__ A, const float* __restrict__ W,
                 const float* __restrict__ bias, float* __restrict__ C,
                 float alpha) {
    extern __shared__ unsigned sh[];
    unsigned (*Ab)[36] = (unsigned(*)[36])sh;                       // 128x36
    unsigned (*Al)[36] = (unsigned(*)[36])(sh + 128*36);            // 128x36
    unsigned (*Bb)[36] = (unsigned(*)[36])(sh + 2*128*36);          // 64x36
    unsigned (*Bl)[36] = (unsigned(*)[36])(sh + 2*128*36 + 64*36);  // 64x36

    const int tid  = threadIdx.x;
    const int lane = tid & 31;
    const int warp = tid >> 5;
    const int g = lane >> 2, c = lane & 3;
    const int wm = warp & 3, wn = warp >> 2;     // 4 warps along M, 2 along N
    const int m0 = blockIdx.y * 128, n0 = blockIdx.x * 64;

    float acc[2][4][4] = {};

    for (int kt = 0; kt < 512; kt += 32) {
        __syncthreads();
        // Load + split A (128x32)
        #pragma unroll
        for (int i = 0; i < 4; i++) {
            const int f = tid + i * 256;          // 0..1023
            const int r = f >> 3, col = (f & 7) * 4;
            float4 v = *(const float4*)(A + (size_t)(m0 + r) * 512 + kt + col);
            float vv[4] = {v.x, v.y, v.z, v.w};
            #pragma unroll
            for (int j = 0; j < 4; j++) {
                unsigned hi = f2t(vv[j]);
                Ab[r][col + j] = hi;
                Al[r][col + j] = f2t(vv[j] - __uint_as_float(hi));
            }
        }
        // Load + split W (64x32)
        #pragma unroll
        for (int i = 0; i < 2; i++) {
            const int f = tid + i * 256;          // 0..511
            const int r = f >> 3, col = (f & 7) * 4;
            float4 v = *(const float4*)(W + (size_t)(n0 + r) * 512 + kt + col);
            float vv[4] = {v.x, v.y, v.z, v.w};
            #pragma unroll
            for (int j = 0; j < 4; j++) {
                unsigned hi = f2t(vv[j]);
                Bb[r][col + j] = hi;
                Bl[r][col + j] = f2t(vv[j] - __uint_as_float(hi));
            }
        }
        __syncthreads();

        #pragma unroll
        for (int d = 0; d < 4; d++) {
            const int k8 = d * 8;
            unsigned ab[2][4], al[2][4], bb[4][2], bl[4][2];
            #pragma unroll
            for (int mi = 0; mi < 2; mi++) {
                const int rb = wm * 32 + mi * 16;
                ab[mi][0] = Ab[rb + g][k8 + c];     ab[mi][1] = Ab[rb + g + 8][k8 + c];
                ab[mi][2] = Ab[rb + g][k8 + c + 4]; ab[mi][3] = Ab[rb + g + 8][k8 + c + 4];
                al[mi][0] = Al[rb + g][k8 + c];     al[mi][1] = Al[rb + g + 8][k8 + c];
                al[mi][2] = Al[rb + g][k8 + c + 4]; al[mi][3] = Al[rb + g + 8][k8 + c + 4];
            }
            #pragma unroll
            for (int ni = 0; ni < 4; ni++) {
                const int cb = wn * 32 + ni * 8;
                bb[ni][0] = Bb[cb + g][k8 + c];  bb[ni][1] = Bb[cb + g][k8 + c + 4];
                bl[ni][0] = Bl[cb + g][k8 + c];  bl[ni][1] = Bl[cb + g][k8 + c + 4];
            }
            #pragma unroll
            for (int mi = 0; mi < 2; mi++)
                #pragma unroll
                for (int ni = 0; ni < 4; ni++) {
                    mma8(acc[mi][ni], ab[mi][0], ab[mi][1], ab[mi][2], ab[mi][3], bb[ni][0], bb[ni][1]);
                    mma8(acc[mi][ni], ab[mi][0], ab[mi][1], ab[mi][2], ab[mi][3], bl[ni][0], bl[ni][1]);
                    mma8(acc[mi][ni], al[mi][0], al[mi][1], al[mi][2], al[mi][3], bb[ni][0], bb[ni][1]);
                }
        }
    }

    // Epilogue
    #pragma unroll
    for (int mi = 0; mi < 2; mi++) {
        const int r0 = m0 + wm * 32 + mi * 16 + g;
        #pragma unroll
        for (int ni = 0; ni < 4; ni++) {
            const int cc = n0 + wn * 32 + ni * 8 + c * 2;
            const float b0 = bias[cc], b1 = bias[cc + 1];
            float v[4];
            v[0] = (acc[mi][ni][0] + b0) * alpha;   // (r0,   cc)
            v[1] = (acc[mi][ni][1] + b1) * alpha;   // (r0,   cc+1)
            v[2] = (acc[mi][ni][2] + b0) * alpha;   // (r0+8, cc)
            v[3] = (acc[mi][ni][3] + b1) * alpha;   // (r0+8, cc+1)
            #pragma unroll
            for (int p = 0; p < 2; p++) {
                const int m = r0 + p * 8;
                #pragma unroll
                for (int q = 0; q < 2; q++) {
                    const int n = cc + q;
                    const float val = v[p * 2 + q];
                    if (MODE == 0) {
                        C[(size_t)m * 512 + n] = val;
                    } else {
                        const int b_ = m >> 11, s_ = m & 2047;
                        const int h_ = n >> 6, dk = n & 63;
                        C[(((size_t)(b_ * HH + h_)) * SS + s_) * DK + dk] = val;
                    }
                }
            }
        }
    }
}

// ---------------------------------------------------------------------------
// Flash attention, tf32 mma. Block = 128 q-rows, 8 warps (16 rows each),
// streams kv in 64-chunks. Q pre-scaled by 1/8.
// ---------------------------------------------------------------------------
__global__ __launch_bounds__(256)
void attn_kernel(const float* __restrict__ Q, const float* __restrict__ K,
                 const float* __restrict__ V, float* __restrict__ Out) {
    extern __shared__ unsigned sh[];
    unsigned (*Qs)[68] = (unsigned(*)[68])sh;                              // 128x68
    unsigned (*Ks)[68] = (unsigned(*)[68])(sh + 128*68);                   // 64x68
    unsigned (*Vs)[72] = (unsigned(*)[72])(sh + 128*68 + 64*68);           // 64x72
    unsigned (*Ps)[68] = (unsigned(*)[68])(sh + 128*68 + 64*68 + 64*72);   // 128x68

    const int tid  = threadIdx.x;
    const int lane = tid & 31;
    const int warp = tid >> 5;
    const int g = lane >> 2, c = lane & 3;
    const int wr = warp * 16;
    const int qt = blockIdx.x;    // 0..15
    const int bh = blockIdx.y;    // 0..15

    const float* Qb = Q + (size_t)bh * SS * DK + (size_t)qt * 128 * DK;
    const float* Kb = K + (size_t)bh * SS * DK;
    const float* Vb = V + (size_t)bh * SS * DK;

    // Load Q tile -> tf32 smem
    #pragma unroll
    for (int i = 0; i < 8; i++) {
        const int f = tid + i * 256;     // 0..2047
        const int r = f >> 4, col = (f & 15) * 4;
        float4 v = *(const float4*)(Qb + r * 64 + col);
        Qs[r][col]     = f2t(v.x); Qs[r][col + 1] = f2t(v.y);
        Qs[r][col + 2] = f2t(v.z); Qs[r][col + 3] = f2t(v.w);
    }

    float O[8][4] = {};
    float m0r = -1e30f, m1r = -1e30f, l0 = 0.f, l1 = 0.f;

    for (int kt = 0; kt < 32; kt++) {
        __syncthreads();   // prior iteration's Ks/Vs/Ps reads complete
        #pragma unroll
        for (int i = 0; i < 4; i++) {
            const int f = tid + i * 256;     // 0..1023
            const int r = f >> 4, col = (f & 15) * 4;
            float4 kv = *(const float4*)(Kb + (size_t)(kt * 64 + r) * 64 + col);
            Ks[r][col]     = f2t(kv.x); Ks[r][col + 1] = f2t(kv.y);
            Ks[r][col + 2] = f2t(kv.z); Ks[r][col + 3] = f2t(kv.w);
            float4 vv = *(const float4*)(Vb + (size_t)(kt * 64 + r) * 64 + col);
            Vs[r][col]     = f2t(vv.x); Vs[r][col + 1] = f2t(vv.y);
            Vs[r][col + 2] = f2t(vv.z); Vs[r][col + 3] = f2t(vv.w);
        }
        __syncthreads();

        // S = Q K^T  (warp's 16 rows x 64 kv cols)
        float sc[8][4] = {};
        #pragma unroll
        for (int d = 0; d < 8; d++) {
            const int k8 = d * 8;
            const unsigned a0 = Qs[wr + g][k8 + c];
            const unsigned a1 = Qs[wr + g + 8][k8 + c];
            const unsigned a2 = Qs[wr + g][k8 + c + 4];
            const unsigned a3 = Qs[wr + g + 8][k8 + c + 4];
            #pragma unroll
            for (int ni = 0; ni < 8; ni++) {
                const unsigned b0 = Ks[ni * 8 + g][k8 + c];
                const unsigned b1 = Ks[ni * 8 + g][k8 + c + 4];
                mma8(sc[ni], a0, a1, a2, a3, b0, b1);
            }
        }

        // Online softmax: thread owns rows (wr+g) [idx 0,1] and (wr+g+8) [idx 2,3]
        {
            float mx = -1e30f;
            #pragma unroll
            for (int ni = 0; ni < 8; ni++) mx = fmaxf(mx, fmaxf(sc[ni][0], sc[ni][1]));
            mx = fmaxf(mx, __shfl_xor_sync(0xffffffffu, mx, 1));
            mx = fmaxf(mx, __shfl_xor_sync(0xffffffffu, mx, 2));
            const float mn = fmaxf(m0r, mx);
            const float corr = __expf(m0r - mn);
            m0r = mn;
            float s = 0.f;
            #pragma unroll
            for (int ni = 0; ni < 8; ni++) {
                sc[ni][0] = __expf(sc[ni][0] - mn);
                sc[ni][1] = __expf(sc[ni][1] - mn);
                s += sc[ni][0] + sc[ni][1];
            }
            s += __shfl_xor_sync(0xffffffffu, s, 1);
            s += __shfl_xor_sync(0xffffffffu, s, 2);
            l0 = l0 * corr + s;
            #pragma unroll
            for (int ni = 0; ni < 8; ni++) { O[ni][0] *= corr; O[ni][1] *= corr; }
        }
        {
            float mx = -1e30f;
            #pragma unroll
            for (int ni = 0; ni < 8; ni++) mx = fmaxf(mx, fmaxf(sc[ni][2], sc[ni][3]));
            mx = fmaxf(mx, __shfl_xor_sync(0xffffffffu, mx, 1));
            mx = fmaxf(mx, __shfl_xor_sync(0xffffffffu, mx, 2));
            const float mn = fmaxf(m1r, mx);
            const float corr = __expf(m1r - mn);
            m1r = mn;
            float s = 0.f;
            #pragma unroll
            for (int ni = 0; ni < 8; ni++) {
                sc[ni][2] = __expf(sc[ni][2] - mn);
                sc[ni][3] = __expf(sc[ni][3] - mn);
                s += sc[ni][2] + sc[ni][3];
            }
            s += __shfl_xor_sync(0xffffffffu, s, 1);
            s += __shfl_xor_sync(0xffffffffu, s, 2);
            l1 = l1 * corr + s;
            #pragma unroll
            for (int ni = 0; ni < 8; ni++) { O[ni][2] *= corr; O[ni][3] *= corr; }
        }

        // Stage P (warp-private rows) for fragment relayout
        #pragma unroll
        for (int ni = 0; ni < 8; ni++) {
            const int cc = ni * 8 + c * 2;
            Ps[wr + g][cc]         = f2t(sc[ni][0]);
            Ps[wr + g][cc + 1]     = f2t(sc[ni][1]);
            Ps[wr + g + 8][cc]     = f2t(sc[ni][2]);
            Ps[wr + g + 8][cc + 1] = f2t(sc[ni][3]);
        }
        __syncwarp();

        // O += P @ V
        #pragma unroll
        for (int d = 0; d < 8; d++) {
            const int k8 = d * 8;
            const unsigned a0 = Ps[wr + g][k8 + c];
            const unsigned a1 = Ps[wr + g + 8][k8 + c];
            const unsigned a2 = Ps[wr + g][k8 + c + 4];
            const unsigned a3 = Ps[wr + g + 8][k8 + c + 4];
            #pragma unroll
            for (int ni = 0; ni < 8; ni++) {
                const unsigned b0 = Vs[k8 + c][ni * 8 + g];
                const unsigned b1 = Vs[k8 + c + 4][ni * 8 + g];
                mma8(O[ni], a0, a1, a2, a3, b0, b1);
            }
        }
    }

    // Normalize + write [B,S,D]
    const int b_ = bh >> 3, h_ = bh & 7;
    const float inv0 = 1.0f / l0, inv1 = 1.0f / l1;
    const int s0 = qt * 128 + wr + g;
    float* o0 = Out + ((size_t)(b_ * SS + s0)) * DD + h_ * 64;
    float* o1 = o0 + 8 * DD;
    #pragma unroll
    for (int ni = 0; ni < 8; ni++) {
        const int cc = ni * 8 + c * 2;
        o0[cc]     = O[ni][0] * inv0;
        o0[cc + 1] = O[ni][1] * inv0;
        o1[cc]     = O[ni][2] * inv1;
        o1[cc + 1] = O[ni][3] * inv1;
    }
}

// ---------------------------------------------------------------------------

extern "C" void kernel_launch(void* const* d_in, const int* in_sizes, int n_in,
                              void* d_out, int out_size) {
    const float* x  = (const float*)d_in[0];
    const float* Wq = (const float*)d_in[1];
    const float* bq = (const float*)d_in[2];
    const float* Wk = (const float*)d_in[3];
    const float* bk = (const float*)d_in[4];
    const float* Wv = (const float*)d_in[5];
    const float* bv = (const float*)d_in[6];
    const float* Wo = (const float*)d_in[7];
    const float* bo = (const float*)d_in[8];
    float* out = (float*)d_out;

    float *Q, *K, *V, *attn;
    cudaGetSymbolAddress((void**)&Q, g_Q);
    cudaGetSymbolAddress((void**)&K, g_K);
    cudaGetSymbolAddress((void**)&V, g_V);
    cudaGetSymbolAddress((void**)&attn, g_attn);

    const int proj_smem = (2 * 128 * 36 + 2 * 64 * 36) * 4;     // 55296 B
    const int attn_smem = (128*68 + 64*68 + 64*72 + 128*68) * 4; // 105472 B
    cudaFuncSetAttribute(proj_kernel<0>, cudaFuncAttributeMaxDynamicSharedMemorySize, proj_smem);
    cudaFuncSetAttribute(proj_kernel<1>, cudaFuncAttributeMaxDynamicSharedMemorySize, proj_smem);
    cudaFuncSetAttribute(attn_kernel,    cudaFuncAttributeMaxDynamicSharedMemorySize, attn_smem);

    const dim3 gp(512 / 64, M_TOTAL / 128);   // (8, 32)

    proj_kernel<1><<<gp, 256, proj_smem>>>(x, Wq, bq, Q, 0.125f);
    proj_kernel<1><<<gp, 256, proj_smem>>>(x, Wk, bk, K, 1.0f);
    proj_kernel<1><<<gp, 256, proj_smem>>>(x, Wv, bv, V, 1.0f);

    attn_kernel<<<dim3(16, 16), 256, attn_smem>>>(Q, K, V, attn);

    proj_kernel<0><<<gp, 256, proj_smem>>>(attn, Wo, bo, out, 1.0f);
}